// round 1
// baseline (speedup 1.0000x reference)
#include <cuda_runtime.h>
#include <cstdint>

#define B_ 2
#define L_ 384
#define H_ 256
#define A_ 14
#define BL (B_ * L_)   // 768
#define JP 192         // L_/2: j-pair offset

// ---------------- scratch (static device globals; no allocations) ----------------
__device__ float  g_hw[BL * H_];          // [b*L+i][h]
__device__ float2 g_hu2[B_ * JP * H_];    // [b][jp][h] = {hu[b][jp][h], hu[b][jp+192][h]}

// ---------------- packed f32x2 helpers ----------------
__device__ __forceinline__ unsigned long long pk2(float lo, float hi) {
    unsigned long long r;
    asm("mov.b64 %0, {%1, %2};" : "=l"(r) : "f"(lo), "f"(hi));
    return r;
}
__device__ __forceinline__ void fma2(unsigned long long& d, unsigned long long a, unsigned long long b) {
    asm("fma.rn.f32x2 %0, %1, %2, %0;" : "+l"(d) : "l"(a), "l"(b));
}
__device__ __forceinline__ void upk2(unsigned long long v, float& lo, float& hi) {
    asm("mov.b64 {%0, %1}, %2;" : "=f"(lo), "=f"(hi) : "l"(v));
}

// ---------------- kernel 1: hw = h@Wx^T+b, hu = h@Ux^T+b (paired layout) ----------------
// grid (12, 8, 2): 64x32 C-tile, z selects weight matrix. block 128, 4x4 micro-tile.
__global__ __launch_bounds__(128) void gemm_k(
    const float* __restrict__ h,
    const float* __restrict__ Wx, const float* __restrict__ Wxb,
    const float* __restrict__ Ux, const float* __restrict__ Uxb)
{
    const int z = blockIdx.z;
    const float* W    = z ? Ux  : Wx;
    const float* bias = z ? Uxb : Wxb;
    const int m0 = blockIdx.x * 64;
    const int n0 = blockIdx.y * 32;

    __shared__ float As[16][64];   // [k][m]
    __shared__ float Bs[16][32];   // [k][n]

    const int tid = threadIdx.x;
    const int tm = tid & 15, tn = tid >> 4;

    float acc[4][4] = {};

    for (int k0 = 0; k0 < H_; k0 += 16) {
        // stage A: 64 rows x 16 k = 256 float4
        #pragma unroll
        for (int q = 0; q < 2; q++) {
            int idx = tid + q * 128;
            int row = idx >> 2, kq = (idx & 3) * 4;
            float4 v = *(const float4*)&h[(m0 + row) * H_ + k0 + kq];
            As[kq + 0][row] = v.x; As[kq + 1][row] = v.y;
            As[kq + 2][row] = v.z; As[kq + 3][row] = v.w;
        }
        // stage B: 32 rows x 16 k = 128 float4
        {
            int row = tid >> 2, kq = (tid & 3) * 4;
            float4 v = *(const float4*)&W[(n0 + row) * H_ + k0 + kq];
            Bs[kq + 0][row] = v.x; Bs[kq + 1][row] = v.y;
            Bs[kq + 2][row] = v.z; Bs[kq + 3][row] = v.w;
        }
        __syncthreads();
        #pragma unroll
        for (int k = 0; k < 16; k++) {
            float4 a4 = *(const float4*)&As[k][tm * 4];
            float4 b4 = *(const float4*)&Bs[k][tn * 4];
            float av[4] = {a4.x, a4.y, a4.z, a4.w};
            float bv[4] = {b4.x, b4.y, b4.z, b4.w};
            #pragma unroll
            for (int r = 0; r < 4; r++)
                #pragma unroll
                for (int c = 0; c < 4; c++)
                    acc[r][c] += av[r] * bv[c];
        }
        __syncthreads();
    }

    #pragma unroll
    for (int r = 0; r < 4; r++) {
        int m = m0 + tm * 4 + r;
        #pragma unroll
        for (int c = 0; c < 4; c++) {
            int n = n0 + tn * 4 + c;
            float val = acc[r][c] + bias[n];
            if (z == 0) {
                g_hw[m * H_ + n] = val;
            } else {
                int b = m / L_, j = m % L_;
                int jp = (j < JP) ? j : j - JP;
                float* p = (float*)&g_hu2[(b * JP + jp) * H_ + n];
                p[(j < JP) ? 0 : 1] = val;
            }
        }
    }
}

// ---------------- kernel 2: fused pairwise gate + fold ----------------
// One block = (batch b, i-pair {i0, i0+1}). 192 threads; thread t owns j-pair (t, t+192).
// Accumulators: acc[i][jl][ap] packed f32x2 over a-pairs (a=2ap, 2ap+1). 28 x u64.
#define KC 32
#define NCH (H_ / KC)     // 8 chunks
#define HUPITCH 34        // float2 pitch per jp-row in shared (pad for banks + f4 align)
#define SMEM_BYTES ((7 * 256 + 2 * 128) * 8 + 192 * HUPITCH * 8)  // 14336+2048+52224 = 68608

__global__ __launch_bounds__(192) void pair_k(
    const float* __restrict__ X, const int* __restrict__ mask,
    const float* __restrict__ Txw, const float* __restrict__ Txb,
    float* __restrict__ out)
{
    extern __shared__ float smem[];
    float2* tx2  = (float2*)smem;              // [7 a-pairs][256 h] = {T[2ap][h], T[2ap+1][h]}
    float2* hw2  = tx2 + 7 * 256;              // [2 i][128 h2]     = {hw[2h2], hw[2h2+1]}
    float*  uni  = (float*)(hw2 + 2 * 128);    // union: hu chunk  |  gate buffer
    float2* hu   = (float2*)uni;               // [192 jp][HUPITCH] chunk of KC h's
    float*  gate = uni;                        // [2 i][384 j][14 a]
    __shared__ float s_red[2][A_][4];

    const int t  = threadIdx.x;
    const int b  = blockIdx.x / (L_ / 2);
    const int i0 = (blockIdx.x % (L_ / 2)) * 2;

    // prologue staging: Tx a-pairs and hw h-pairs
    for (int idx = t; idx < 7 * 256; idx += 192) {
        int ap = idx >> 8, hh = idx & 255;
        tx2[idx] = make_float2(Txw[(2 * ap) * H_ + hh], Txw[(2 * ap + 1) * H_ + hh]);
    }
    for (int idx = t; idx < 2 * 128; idx += 192) {
        int i = idx >> 7, h2 = idx & 127;
        hw2[idx] = *(const float2*)&g_hw[(b * L_ + i0 + i) * H_ + 2 * h2];
    }

    unsigned long long acc[2][2][7];
    #pragma unroll
    for (int i = 0; i < 2; i++)
        #pragma unroll
        for (int jl = 0; jl < 2; jl++)
            #pragma unroll
            for (int ap = 0; ap < 7; ap++)
                acc[i][jl][ap] = 0ull;

    for (int kc = 0; kc < NCH; kc++) {
        __syncthreads();   // also covers prologue before first chunk
        // stage hu chunk: 192 jp x KC h (float2) = 3072 float4
        #pragma unroll
        for (int q = 0; q < 16; q++) {
            int idx = t + q * 192;
            int row = idx >> 4, col = idx & 15;
            float4 v = *(const float4*)&g_hu2[(b * JP + row) * H_ + kc * KC + col * 2];
            *(float4*)&hu[row * HUPITCH + col * 2] = v;
        }
        __syncthreads();
        #pragma unroll 4
        for (int hl = 0; hl < KC / 2; hl++) {
            int h2 = kc * (KC / 2) + hl;   // global h/2
            float4 hu4 = *(const float4*)&hu[t * HUPITCH + 2 * hl];
            // hu4 = {hu_j0(h), hu_j1(h), hu_j0(h+1), hu_j1(h+1)}
            unsigned long long rd[2][2][2];   // [i][jl][which-h], dup-packed relu
            #pragma unroll
            for (int i = 0; i < 2; i++) {
                float2 w = hw2[i * 128 + h2];
                float r00 = fmaxf(hu4.x + w.x, 0.f);
                float r10 = fmaxf(hu4.y + w.x, 0.f);
                float r01 = fmaxf(hu4.z + w.y, 0.f);
                float r11 = fmaxf(hu4.w + w.y, 0.f);
                rd[i][0][0] = pk2(r00, r00);
                rd[i][1][0] = pk2(r10, r10);
                rd[i][0][1] = pk2(r01, r01);
                rd[i][1][1] = pk2(r11, r11);
            }
            #pragma unroll
            for (int ap = 0; ap < 7; ap++) {
                unsigned long long tA = *(const unsigned long long*)&tx2[ap * 256 + 2 * h2];
                unsigned long long tB = *(const unsigned long long*)&tx2[ap * 256 + 2 * h2 + 1];
                #pragma unroll
                for (int i = 0; i < 2; i++) {
                    fma2(acc[i][0][ap], rd[i][0][0], tA);
                    fma2(acc[i][1][ap], rd[i][1][0], tA);
                    fma2(acc[i][0][ap], rd[i][0][1], tB);
                    fma2(acc[i][1][ap], rd[i][1][1], tB);
                }
            }
        }
    }

    __syncthreads();   // everyone done reading hu before overwriting union with gates
    #pragma unroll
    for (int i = 0; i < 2; i++)
        #pragma unroll
        for (int jl = 0; jl < 2; jl++) {
            int j = t + jl * JP;
            #pragma unroll
            for (int ap = 0; ap < 7; ap++) {
                float lo, hi; upk2(acc[i][jl][ap], lo, hi);
                gate[(i * L_ + j) * A_ + 2 * ap]     = lo;
                gate[(i * L_ + j) * A_ + 2 * ap + 1] = hi;
            }
        }
    __syncthreads();

    // phase A: reduce over j. 112 threads: (i, a, q): q<3 -> S_c, q==3 -> G
    float msum = 0.f;
    if (t < 112) {
        int i = t / 56, r = t % 56, a = r >> 2, q = r & 3;
        float txb = Txb[a];
        float accv = 0.f;
        const float* Xb = X + (size_t)b * L_ * A_ * 3;
        const int* mb = mask + b * L_;
        for (int j = 0; j < L_; j++) {
            float m = (float)mb[j];
            float g = (gate[(i * L_ + j) * A_ + a] + txb) * m;
            msum += m;
            accv += (q == 3) ? g : g * Xb[(j * A_ + a) * 3 + q];
        }
        s_red[i][a][q] = accv;
    }
    __syncthreads();

    // phase B: 84 threads write outputs (i, a, c)
    if (t < 84) {
        int i = t / 42, r = t % 42, a = r / 3, c = r % 3;
        float denom = 1e-6f + msum;    // t<84 < 112: msum was computed above
        float Xi = X[((size_t)(b * L_ + i0 + i) * A_ + a) * 3 + c];
        float f = (Xi * s_red[i][a][3] - s_red[i][a][c]) / denom;
        f = fminf(fmaxf(f, -20.f), 20.f);
        out[((size_t)(b * L_ + i0 + i) * A_ + a) * 3 + c] = Xi + f;
    }
}

// ---------------- launch ----------------
extern "C" void kernel_launch(void* const* d_in, const int* in_sizes, int n_in,
                              void* d_out, int out_size) {
    const float* h    = (const float*)d_in[0];
    const float* X    = (const float*)d_in[1];
    const int*   mask = (const int*)  d_in[2];
    const float* Wxw  = (const float*)d_in[3];
    const float* Wxb  = (const float*)d_in[4];
    const float* Uxw  = (const float*)d_in[5];
    const float* Uxb  = (const float*)d_in[6];
    const float* Txw  = (const float*)d_in[7];
    const float* Txb  = (const float*)d_in[8];
    float* out = (float*)d_out;

    cudaFuncSetAttribute(pair_k, cudaFuncAttributeMaxDynamicSharedMemorySize, SMEM_BYTES);

    gemm_k<<<dim3(12, 8, 2), 128>>>(h, Wxw, Wxb, Uxw, Uxb);
    pair_k<<<dim3(B_ * (L_ / 2)), 192, SMEM_BYTES>>>(X, mask, Txw, Txb, out);
}

// round 3
// speedup vs baseline: 1.0913x; 1.0913x over previous
#include <cuda_runtime.h>
#include <cstdint>

#define B_ 2
#define L_ 384
#define H_ 256
#define A_ 14
#define BL (B_ * L_)   // 768
#define JP 192         // L_/2: j-pair offset

// ---------------- scratch (static device globals; no allocations) ----------------
__device__ float  g_hw[BL * H_];          // [b*L+i][h]
__device__ float2 g_hu2[B_ * JP * H_];    // [b][jp][h] = {hu[b][jp][h], hu[b][jp+192][h]}

// ---------------- packed f32x2 helpers ----------------
__device__ __forceinline__ unsigned long long pk2(float lo, float hi) {
    unsigned long long r;
    asm("mov.b64 %0, {%1, %2};" : "=l"(r) : "f"(lo), "f"(hi));
    return r;
}
__device__ __forceinline__ void fma2(unsigned long long& d, unsigned long long a, unsigned long long b) {
    asm("fma.rn.f32x2 %0, %1, %2, %0;" : "+l"(d) : "l"(a), "l"(b));
}
__device__ __forceinline__ void upk2(unsigned long long v, float& lo, float& hi) {
    asm("mov.b64 {%0, %1}, %2;" : "=f"(lo), "=f"(hi) : "l"(v));
}

// ---------------- kernel 1: hw = h@Wx^T+b, hu = h@Ux^T+b (paired layout) ----------------
__global__ __launch_bounds__(128) void gemm_k(
    const float* __restrict__ h,
    const float* __restrict__ Wx, const float* __restrict__ Wxb,
    const float* __restrict__ Ux, const float* __restrict__ Uxb)
{
    const int z = blockIdx.z;
    const float* W    = z ? Ux  : Wx;
    const float* bias = z ? Uxb : Wxb;
    const int m0 = blockIdx.x * 64;
    const int n0 = blockIdx.y * 32;

    __shared__ float As[16][64];
    __shared__ float Bs[16][32];

    const int tid = threadIdx.x;
    const int tm = tid & 15, tn = tid >> 4;

    float acc[4][4] = {};

    for (int k0 = 0; k0 < H_; k0 += 16) {
        #pragma unroll
        for (int q = 0; q < 2; q++) {
            int idx = tid + q * 128;
            int row = idx >> 2, kq = (idx & 3) * 4;
            float4 v = *(const float4*)&h[(m0 + row) * H_ + k0 + kq];
            As[kq + 0][row] = v.x; As[kq + 1][row] = v.y;
            As[kq + 2][row] = v.z; As[kq + 3][row] = v.w;
        }
        {
            int row = tid >> 2, kq = (tid & 3) * 4;
            float4 v = *(const float4*)&W[(n0 + row) * H_ + k0 + kq];
            Bs[kq + 0][row] = v.x; Bs[kq + 1][row] = v.y;
            Bs[kq + 2][row] = v.z; Bs[kq + 3][row] = v.w;
        }
        __syncthreads();
        #pragma unroll
        for (int k = 0; k < 16; k++) {
            float4 a4 = *(const float4*)&As[k][tm * 4];
            float4 b4 = *(const float4*)&Bs[k][tn * 4];
            float av[4] = {a4.x, a4.y, a4.z, a4.w};
            float bv[4] = {b4.x, b4.y, b4.z, b4.w};
            #pragma unroll
            for (int r = 0; r < 4; r++)
                #pragma unroll
                for (int c = 0; c < 4; c++)
                    acc[r][c] += av[r] * bv[c];
        }
        __syncthreads();
    }

    #pragma unroll
    for (int r = 0; r < 4; r++) {
        int m = m0 + tm * 4 + r;
        #pragma unroll
        for (int c = 0; c < 4; c++) {
            int n = n0 + tn * 4 + c;
            float val = acc[r][c] + bias[n];
            if (z == 0) {
                g_hw[m * H_ + n] = val;
            } else {
                int b = m / L_, j = m % L_;
                int jp = (j < JP) ? j : j - JP;
                float* p = (float*)&g_hu2[(b * JP + jp) * H_ + n];
                p[(j < JP) ? 0 : 1] = val;
            }
        }
    }
}

// ---------------- kernel 2: fused pairwise gate + fold ----------------
// One block = (batch b, i-pair). 192 threads; thread t owns j-pair (t, t+192).
#define KC 32
#define NCH (H_ / KC)     // 8 chunks
#define HUPITCH 34        // float2 pitch (pad -> conflict-free LDS.128, safe over-read)
// txp: 7 a-pairs x 128 h2 x 16B = 14336 ; hw2: 2*128*8 = 2048 ; union(hu 52224, gate 43008)
#define SMEM_BYTES (14336 + 2048 + 192 * HUPITCH * 8)  // 68608

__global__ __launch_bounds__(192, 3) void pair_k(
    const float* __restrict__ X, const int* __restrict__ mask,
    const float* __restrict__ Txw, const float* __restrict__ Txb,
    float* __restrict__ out)
{
    extern __shared__ float smem[];
    float4* txp  = (float4*)smem;              // [7 ap][128 h2] = {T[2ap][2h2],T[2ap+1][2h2],T[2ap][2h2+1],T[2ap+1][2h2+1]}
    float2* hw2  = (float2*)(txp + 7 * 128);   // [2 i][128 h2]
    float*  uni  = (float*)(hw2 + 2 * 128);    // union: hu chunk | gate buffer
    float2* hu   = (float2*)uni;               // [192 jp][HUPITCH]
    float*  gate = uni;                        // [2 i][384 j][14 a]
    __shared__ float s_red[2][A_][4];

    const int t  = threadIdx.x;
    const int b  = blockIdx.x / (L_ / 2);
    const int i0 = (blockIdx.x % (L_ / 2)) * 2;

    // prologue staging: Tx quad-packed, hw h-pairs
    for (int idx = t; idx < 7 * 128; idx += 192) {
        int ap = idx >> 7, h2 = idx & 127;
        float4 v;
        v.x = Txw[(2 * ap)     * H_ + 2 * h2];
        v.y = Txw[(2 * ap + 1) * H_ + 2 * h2];
        v.z = Txw[(2 * ap)     * H_ + 2 * h2 + 1];
        v.w = Txw[(2 * ap + 1) * H_ + 2 * h2 + 1];
        txp[idx] = v;
    }
    for (int idx = t; idx < 2 * 128; idx += 192) {
        int i = idx >> 7, h2 = idx & 127;
        hw2[idx] = *(const float2*)&g_hw[(b * L_ + i0 + i) * H_ + 2 * h2];
    }

    unsigned long long acc[2][2][7];
    #pragma unroll
    for (int i = 0; i < 2; i++)
        #pragma unroll
        for (int jl = 0; jl < 2; jl++)
            #pragma unroll
            for (int ap = 0; ap < 7; ap++)
                acc[i][jl][ap] = 0ull;

    for (int kc = 0; kc < NCH; kc++) {
        __syncthreads();   // also covers prologue before first chunk
        // stage hu chunk: 192 jp x KC h (float2) = 3072 float4
        #pragma unroll
        for (int q = 0; q < 16; q++) {
            int idx = t + q * 192;
            int row = idx >> 4, col = idx & 15;
            float4 v = *(const float4*)&g_hu2[(b * JP + row) * H_ + kc * KC + col * 2];
            *(float4*)&hu[row * HUPITCH + col * 2] = v;
        }
        __syncthreads();

        float4 cur = *(const float4*)&hu[t * HUPITCH];   // prefetched hl=0
        #pragma unroll 4
        for (int hl = 0; hl < KC / 2; hl++) {
            // prefetch next (hl=15 reads pad bytes inside the row; harmless)
            float4 nxt = *(const float4*)&hu[t * HUPITCH + 2 * (hl + 1)];
            int h2 = kc * (KC / 2) + hl;   // global h/2
            // cur = {hu_j0(h), hu_j1(h), hu_j0(h+1), hu_j1(h+1)}
            unsigned long long rd[2][2][2];   // [i][jl][which-h], dup-packed relu
            #pragma unroll
            for (int i = 0; i < 2; i++) {
                float2 w = hw2[i * 128 + h2];
                float r00 = fmaxf(cur.x + w.x, 0.f);
                float r10 = fmaxf(cur.y + w.x, 0.f);
                float r01 = fmaxf(cur.z + w.y, 0.f);
                float r11 = fmaxf(cur.w + w.y, 0.f);
                rd[i][0][0] = pk2(r00, r00);
                rd[i][1][0] = pk2(r10, r10);
                rd[i][0][1] = pk2(r01, r01);
                rd[i][1][1] = pk2(r11, r11);
            }
            #pragma unroll
            for (int ap = 0; ap < 7; ap++) {
                ulonglong2 tv = *(const ulonglong2*)&txp[ap * 128 + h2];  // {tA, tB}
                #pragma unroll
                for (int i = 0; i < 2; i++) {
                    fma2(acc[i][0][ap], rd[i][0][0], tv.x);
                    fma2(acc[i][1][ap], rd[i][1][0], tv.x);
                    fma2(acc[i][0][ap], rd[i][0][1], tv.y);
                    fma2(acc[i][1][ap], rd[i][1][1], tv.y);
                }
            }
            cur = nxt;
        }
    }

    __syncthreads();   // everyone done reading hu before overwriting union with gates
    #pragma unroll
    for (int i = 0; i < 2; i++)
        #pragma unroll
        for (int jl = 0; jl < 2; jl++) {
            int j = t + jl * JP;
            #pragma unroll
            for (int ap = 0; ap < 7; ap++) {
                float lo, hi; upk2(acc[i][jl][ap], lo, hi);
                gate[(i * L_ + j) * A_ + 2 * ap]     = lo;
                gate[(i * L_ + j) * A_ + 2 * ap + 1] = hi;
            }
        }
    __syncthreads();

    // phase A: reduce over j. 112 threads: (i, a, q): q<3 -> S_c, q==3 -> G
    float msum = 0.f;
    if (t < 112) {
        int i = t / 56, r = t % 56, a = r >> 2, q = r & 3;
        float txb = Txb[a];
        float accv = 0.f;
        const float* Xb = X + (size_t)b * L_ * A_ * 3;
        const int* mb = mask + b * L_;
        for (int j = 0; j < L_; j++) {
            float m = (float)mb[j];
            float g = (gate[(i * L_ + j) * A_ + a] + txb) * m;
            msum += m;
            accv += (q == 3) ? g : g * Xb[(j * A_ + a) * 3 + q];
        }
        s_red[i][a][q] = accv;
    }
    __syncthreads();

    // phase B: 84 threads write outputs (i, a, c)
    if (t < 84) {
        int i = t / 42, r = t % 42, a = r / 3, c = r % 3;
        float denom = 1e-6f + msum;    // t<84 < 112: msum computed above
        float Xi = X[((size_t)(b * L_ + i0 + i) * A_ + a) * 3 + c];
        float f = (Xi * s_red[i][a][3] - s_red[i][a][c]) / denom;
        f = fminf(fmaxf(f, -20.f), 20.f);
        out[((size_t)(b * L_ + i0 + i) * A_ + a) * 3 + c] = Xi + f;
    }
}

// ---------------- launch ----------------
extern "C" void kernel_launch(void* const* d_in, const int* in_sizes, int n_in,
                              void* d_out, int out_size) {
    const float* h    = (const float*)d_in[0];
    const float* X    = (const float*)d_in[1];
    const int*   mask = (const int*)  d_in[2];
    const float* Wxw  = (const float*)d_in[3];
    const float* Wxb  = (const float*)d_in[4];
    const float* Uxw  = (const float*)d_in[5];
    const float* Uxb  = (const float*)d_in[6];
    const float* Txw  = (const float*)d_in[7];
    const float* Txb  = (const float*)d_in[8];
    float* out = (float*)d_out;

    cudaFuncSetAttribute(pair_k, cudaFuncAttributeMaxDynamicSharedMemorySize, SMEM_BYTES);

    gemm_k<<<dim3(12, 8, 2), 128>>>(h, Wxw, Wxb, Uxw, Uxb);
    pair_k<<<dim3(B_ * (L_ / 2)), 192, SMEM_BYTES>>>(X, mask, Txw, Txb, out);
}

// round 4
// speedup vs baseline: 1.1808x; 1.0820x over previous
#include <cuda_runtime.h>
#include <cstdint>

#define B_ 2
#define L_ 384
#define H_ 256
#define A_ 14
#define BL (B_ * L_)   // 768
#define JP 192         // L_/2: j-pair offset

// ---------------- scratch (static device globals; no allocations) ----------------
__device__ float  g_hw[BL * H_];          // [b*L+i][h]
__device__ float2 g_hu2[B_ * JP * H_];    // [b][jp][h] = {hu[b][jp][h], hu[b][jp+192][h]}

// ---------------- packed f32x2 + cp.async helpers ----------------
__device__ __forceinline__ unsigned long long pk2(float lo, float hi) {
    unsigned long long r;
    asm("mov.b64 %0, {%1, %2};" : "=l"(r) : "f"(lo), "f"(hi));
    return r;
}
__device__ __forceinline__ void fma2(unsigned long long& d, unsigned long long a, unsigned long long b) {
    asm("fma.rn.f32x2 %0, %1, %2, %0;" : "+l"(d) : "l"(a), "l"(b));
}
__device__ __forceinline__ void upk2(unsigned long long v, float& lo, float& hi) {
    asm("mov.b64 {%0, %1}, %2;" : "=f"(lo), "=f"(hi) : "l"(v));
}
__device__ __forceinline__ void cp16(uint32_t s, const void* g) {
    asm volatile("cp.async.cg.shared.global [%0], [%1], 16;" :: "r"(s), "l"(g));
}
__device__ __forceinline__ void cp_commit() { asm volatile("cp.async.commit_group;"); }
template<int N> __device__ __forceinline__ void cp_wait() {
    asm volatile("cp.async.wait_group %0;" :: "n"(N));
}

// ---------------- kernel 1: hw = h@Wx^T+b, hu = h@Ux^T+b (paired layout) ----------------
// 32x32 tile, grid (24, 8, 2) = 384 blocks, 128 threads, micro-tile 2x4.
__global__ __launch_bounds__(128) void gemm_k(
    const float* __restrict__ h,
    const float* __restrict__ Wx, const float* __restrict__ Wxb,
    const float* __restrict__ Ux, const float* __restrict__ Uxb)
{
    const int z = blockIdx.z;
    const float* W    = z ? Ux  : Wx;
    const float* bias = z ? Uxb : Wxb;
    const int m0 = blockIdx.x * 32;
    const int n0 = blockIdx.y * 32;

    __shared__ float As[16][32];   // [k][m]
    __shared__ float Bs[16][32];   // [k][n]

    const int tid = threadIdx.x;
    const int tm = tid & 15, tn = tid >> 4;

    float acc[2][4] = {};

    for (int k0 = 0; k0 < H_; k0 += 16) {
        {
            int row = tid >> 2, kq = (tid & 3) * 4;
            float4 a = *(const float4*)&h[(m0 + row) * H_ + k0 + kq];
            As[kq + 0][row] = a.x; As[kq + 1][row] = a.y;
            As[kq + 2][row] = a.z; As[kq + 3][row] = a.w;
            float4 bv = *(const float4*)&W[(n0 + row) * H_ + k0 + kq];
            Bs[kq + 0][row] = bv.x; Bs[kq + 1][row] = bv.y;
            Bs[kq + 2][row] = bv.z; Bs[kq + 3][row] = bv.w;
        }
        __syncthreads();
        #pragma unroll
        for (int k = 0; k < 16; k++) {
            float2 a2 = *(const float2*)&As[k][tm * 2];
            float4 b4 = *(const float4*)&Bs[k][tn * 4];
            acc[0][0] += a2.x * b4.x; acc[0][1] += a2.x * b4.y;
            acc[0][2] += a2.x * b4.z; acc[0][3] += a2.x * b4.w;
            acc[1][0] += a2.y * b4.x; acc[1][1] += a2.y * b4.y;
            acc[1][2] += a2.y * b4.z; acc[1][3] += a2.y * b4.w;
        }
        __syncthreads();
    }

    #pragma unroll
    for (int r = 0; r < 2; r++) {
        int m = m0 + tm * 2 + r;
        #pragma unroll
        for (int c = 0; c < 4; c++) {
            int n = n0 + tn * 4 + c;
            float val = acc[r][c] + bias[n];
            if (z == 0) {
                g_hw[m * H_ + n] = val;
            } else {
                int b = m / L_, j = m % L_;
                int jp = (j < JP) ? j : j - JP;
                float* p = (float*)&g_hu2[(b * JP + jp) * H_ + n];
                p[(j < JP) ? 0 : 1] = val;
            }
        }
    }
}

// ---------------- kernel 2: fused pairwise gate + fold ----------------
// One block = (batch b, i-pair). 192 threads; thread t owns j-pair (t, t+192).
#define KC 16             // h per chunk
#define NCH (H_ / KC)     // 16 chunks
#define HUP 18            // float2 pitch per jp row (pad -> conflict-free + safe over-read)
#define HUBUF_F2 (192 * HUP)          // 3456 float2 per buffer
// floats: txp 7*128*4 = 3584 ; hw2 2*128*2 = 512 ; uni = 2 buffers * 6912 = 13824
#define UNI_OFF_F 4096
#define SMEM_BYTES ((UNI_OFF_F + 2 * HUBUF_F2 * 2) * 4)   // 71680

__global__ __launch_bounds__(192, 3) void pair_k(
    const float* __restrict__ X, const int* __restrict__ mask,
    const float* __restrict__ Txw, const float* __restrict__ Txb,
    float* __restrict__ out)
{
    extern __shared__ float smem[];
    float4* txp  = (float4*)smem;                 // [7 ap][128 h2] quad-packed Tx
    float2* hw2  = (float2*)(smem + 3584);        // [2 i][128 h2]
    float*  uni  = smem + UNI_OFF_F;              // union: 2x hu buffers | gate buffer
    float*  gate = uni;                           // [2 i][384 j][14 a] (pre-masked, pre-biased)
    __shared__ float s_red[2][A_][4];
    __shared__ float s_ms[6];

    const int t  = threadIdx.x;
    const int b  = blockIdx.x / (L_ / 2);
    const int i0 = (blockIdx.x % (L_ / 2)) * 2;

    const uint32_t uni_u32 = (uint32_t)__cvta_generic_to_shared(uni);
    const float2* husrc = g_hu2 + (size_t)b * JP * H_;   // float2 units, [jp][h]

    // prologue staging: Tx quad-packed, hw h-pairs
    for (int idx = t; idx < 7 * 128; idx += 192) {
        int ap = idx >> 7, h2 = idx & 127;
        float4 v;
        v.x = Txw[(2 * ap)     * H_ + 2 * h2];
        v.y = Txw[(2 * ap + 1) * H_ + 2 * h2];
        v.z = Txw[(2 * ap)     * H_ + 2 * h2 + 1];
        v.w = Txw[(2 * ap + 1) * H_ + 2 * h2 + 1];
        txp[idx] = v;
    }
    for (int idx = t; idx < 2 * 128; idx += 192) {
        int i = idx >> 7, h2 = idx & 127;
        hw2[idx] = *(const float2*)&g_hw[(b * L_ + i0 + i) * H_ + 2 * h2];
    }

    unsigned long long acc[2][2][7];
    #pragma unroll
    for (int i = 0; i < 2; i++)
        #pragma unroll
        for (int jl = 0; jl < 2; jl++)
            #pragma unroll
            for (int ap = 0; ap < 7; ap++)
                acc[i][jl][ap] = 0ull;

    // stage chunk 0
    {
        #pragma unroll
        for (int q = 0; q < 8; q++) {
            int idx = t + q * 192, row = idx >> 3, col = idx & 7;
            cp16(uni_u32 + (uint32_t)(row * HUP + col * 2) * 8,
                 husrc + row * H_ + col * 2);
        }
        cp_commit();
    }

    for (int kc = 0; kc < NCH; kc++) {
        if (kc + 1 < NCH) {   // stage next chunk into other buffer
            uint32_t dst = uni_u32 + ((kc + 1) & 1) * (HUBUF_F2 * 8);
            const float2* src = husrc + (kc + 1) * KC;
            #pragma unroll
            for (int q = 0; q < 8; q++) {
                int idx = t + q * 192, row = idx >> 3, col = idx & 7;
                cp16(dst + (uint32_t)(row * HUP + col * 2) * 8,
                     src + row * H_ + col * 2);
            }
            cp_commit();
            cp_wait<1>();
        } else {
            cp_wait<0>();
        }
        __syncthreads();   // staged data visible to all; also covers prologue at kc=0

        const float2* hu = (const float2*)uni + (kc & 1) * HUBUF_F2;
        float4 cur = *(const float4*)&hu[t * HUP];   // prefetched hl=0
        #pragma unroll
        for (int hl = 0; hl < KC / 2; hl++) {
            float4 nxt = *(const float4*)&hu[t * HUP + 2 * (hl + 1)];  // last iter reads pad
            int h2 = kc * (KC / 2) + hl;   // global h/2
            unsigned long long rd[2][2][2];   // [i][jl][which-h], dup-packed relu
            #pragma unroll
            for (int i = 0; i < 2; i++) {
                float2 w = hw2[i * 128 + h2];
                float r00 = fmaxf(cur.x + w.x, 0.f);
                float r10 = fmaxf(cur.y + w.x, 0.f);
                float r01 = fmaxf(cur.z + w.y, 0.f);
                float r11 = fmaxf(cur.w + w.y, 0.f);
                rd[i][0][0] = pk2(r00, r00);
                rd[i][1][0] = pk2(r10, r10);
                rd[i][0][1] = pk2(r01, r01);
                rd[i][1][1] = pk2(r11, r11);
            }
            #pragma unroll
            for (int ap = 0; ap < 7; ap++) {
                ulonglong2 tv = *(const ulonglong2*)&txp[ap * 128 + h2];  // {tA, tB}
                #pragma unroll
                for (int i = 0; i < 2; i++) {
                    fma2(acc[i][0][ap], rd[i][0][0], tv.x);
                    fma2(acc[i][1][ap], rd[i][1][0], tv.x);
                    fma2(acc[i][0][ap], rd[i][0][1], tv.y);
                    fma2(acc[i][1][ap], rd[i][1][1], tv.y);
                }
            }
            cur = nxt;
        }
        __syncthreads();   // all reads of this buffer done before it is restaged
    }

    // ---- gate writeback: fold bias + mask; block msum via shuffles ----
    const float mj[2] = { (float)mask[b * L_ + t], (float)mask[b * L_ + t + JP] };
    {
        float mm = mj[0] + mj[1];
        #pragma unroll
        for (int o = 16; o; o >>= 1) mm += __shfl_xor_sync(0xffffffffu, mm, o);
        if ((t & 31) == 0) s_ms[t >> 5] = mm;
    }
    #pragma unroll
    for (int i = 0; i < 2; i++)
        #pragma unroll
        for (int jl = 0; jl < 2; jl++) {
            int j = t + jl * JP;
            float m = mj[jl];
            #pragma unroll
            for (int ap = 0; ap < 7; ap++) {
                float lo, hi; upk2(acc[i][jl][ap], lo, hi);
                gate[(i * L_ + j) * A_ + 2 * ap]     = (lo + Txb[2 * ap])     * m;
                gate[(i * L_ + j) * A_ + 2 * ap + 1] = (hi + Txb[2 * ap + 1]) * m;
            }
        }
    __syncthreads();

    // phase A: reduce over j. 112 threads: (i, a, q): q<3 -> S_c, q==3 -> G
    if (t < 112) {
        int i = t / 56, r = t % 56, a = r >> 2, q = r & 3;
        float accv = 0.f;
        const float* Xb = X + (size_t)b * L_ * A_ * 3;
        for (int j = 0; j < L_; j++) {
            float g = gate[(i * L_ + j) * A_ + a];
            accv += (q == 3) ? g : g * Xb[(j * A_ + a) * 3 + q];
        }
        s_red[i][a][q] = accv;
    }
    __syncthreads();

    // phase B: 84 threads write outputs (i, a, c)
    if (t < 84) {
        int i = t / 42, r = t % 42, a = r / 3, c = r % 3;
        float denom = 1e-6f + (s_ms[0] + s_ms[1] + s_ms[2] + s_ms[3] + s_ms[4] + s_ms[5]);
        float Xi = X[((size_t)(b * L_ + i0 + i) * A_ + a) * 3 + c];
        float f = (Xi * s_red[i][a][3] - s_red[i][a][c]) / denom;
        f = fminf(fmaxf(f, -20.f), 20.f);
        out[((size_t)(b * L_ + i0 + i) * A_ + a) * 3 + c] = Xi + f;
    }
}

// ---------------- launch ----------------
extern "C" void kernel_launch(void* const* d_in, const int* in_sizes, int n_in,
                              void* d_out, int out_size) {
    const float* h    = (const float*)d_in[0];
    const float* X    = (const float*)d_in[1];
    const int*   mask = (const int*)  d_in[2];
    const float* Wxw  = (const float*)d_in[3];
    const float* Wxb  = (const float*)d_in[4];
    const float* Uxw  = (const float*)d_in[5];
    const float* Uxb  = (const float*)d_in[6];
    const float* Txw  = (const float*)d_in[7];
    const float* Txb  = (const float*)d_in[8];
    float* out = (float*)d_out;

    cudaFuncSetAttribute(pair_k, cudaFuncAttributeMaxDynamicSharedMemorySize, SMEM_BYTES);

    gemm_k<<<dim3(24, 8, 2), 128>>>(h, Wxw, Wxb, Uxw, Uxb);
    pair_k<<<dim3(B_ * (L_ / 2)), 192, SMEM_BYTES>>>(X, mask, Txw, Txb, out);
}

// round 5
// speedup vs baseline: 1.2682x; 1.0739x over previous
#include <cuda_runtime.h>
#include <cstdint>

#define B_ 2
#define L_ 384
#define H_ 256
#define A_ 14
#define BL (B_ * L_)   // 768
#define JP 192         // L_/2: j-pair offset

// ---------------- scratch (static device globals; no allocations) ----------------
__device__ float  g_hw[BL * H_];          // [b*L+i][h]
__device__ float2 g_hu2[B_ * JP * H_];    // [b][jp][h] = {hu[b][jp][h], hu[b][jp+192][h]}

// ---------------- packed f32x2 + cp.async helpers ----------------
__device__ __forceinline__ unsigned long long pk2(float lo, float hi) {
    unsigned long long r;
    asm("mov.b64 %0, {%1, %2};" : "=l"(r) : "f"(lo), "f"(hi));
    return r;
}
__device__ __forceinline__ void fma2(unsigned long long& d, unsigned long long a, unsigned long long b) {
    asm("fma.rn.f32x2 %0, %1, %2, %0;" : "+l"(d) : "l"(a), "l"(b));
}
__device__ __forceinline__ void upk2(unsigned long long v, float& lo, float& hi) {
    asm("mov.b64 {%0, %1}, %2;" : "=f"(lo), "=f"(hi) : "l"(v));
}
__device__ __forceinline__ void cp16(uint32_t s, const void* g) {
    asm volatile("cp.async.cg.shared.global [%0], [%1], 16;" :: "r"(s), "l"(g));
}
__device__ __forceinline__ void cp_commit() { asm volatile("cp.async.commit_group;"); }
template<int N> __device__ __forceinline__ void cp_wait() {
    asm volatile("cp.async.wait_group %0;" :: "n"(N));
}

// ---------------- kernel 1: hw = h@Wx^T+b, hu = h@Ux^T+b (paired layout) ----------------
__global__ __launch_bounds__(128) void gemm_k(
    const float* __restrict__ h,
    const float* __restrict__ Wx, const float* __restrict__ Wxb,
    const float* __restrict__ Ux, const float* __restrict__ Uxb)
{
    const int z = blockIdx.z;
    const float* W    = z ? Ux  : Wx;
    const float* bias = z ? Uxb : Wxb;
    const int m0 = blockIdx.x * 32;
    const int n0 = blockIdx.y * 32;

    __shared__ float As[16][32];
    __shared__ float Bs[16][32];

    const int tid = threadIdx.x;
    const int tm = tid & 15, tn = tid >> 4;

    float acc[2][4] = {};

    for (int k0 = 0; k0 < H_; k0 += 16) {
        {
            int row = tid >> 2, kq = (tid & 3) * 4;
            float4 a = *(const float4*)&h[(m0 + row) * H_ + k0 + kq];
            As[kq + 0][row] = a.x; As[kq + 1][row] = a.y;
            As[kq + 2][row] = a.z; As[kq + 3][row] = a.w;
            float4 bv = *(const float4*)&W[(n0 + row) * H_ + k0 + kq];
            Bs[kq + 0][row] = bv.x; Bs[kq + 1][row] = bv.y;
            Bs[kq + 2][row] = bv.z; Bs[kq + 3][row] = bv.w;
        }
        __syncthreads();
        #pragma unroll
        for (int k = 0; k < 16; k++) {
            float2 a2 = *(const float2*)&As[k][tm * 2];
            float4 b4 = *(const float4*)&Bs[k][tn * 4];
            acc[0][0] += a2.x * b4.x; acc[0][1] += a2.x * b4.y;
            acc[0][2] += a2.x * b4.z; acc[0][3] += a2.x * b4.w;
            acc[1][0] += a2.y * b4.x; acc[1][1] += a2.y * b4.y;
            acc[1][2] += a2.y * b4.z; acc[1][3] += a2.y * b4.w;
        }
        __syncthreads();
    }

    #pragma unroll
    for (int r = 0; r < 2; r++) {
        int m = m0 + tm * 2 + r;
        #pragma unroll
        for (int c = 0; c < 4; c++) {
            int n = n0 + tn * 4 + c;
            float val = acc[r][c] + bias[n];
            if (z == 0) {
                g_hw[m * H_ + n] = val;
            } else {
                int b = m / L_, j = m % L_;
                int jp = (j < JP) ? j : j - JP;
                float* p = (float*)&g_hu2[(b * JP + jp) * H_ + n];
                p[(j < JP) ? 0 : 1] = val;
            }
        }
    }
}

// ---------------- kernel 2: fused pairwise gate + fold ----------------
// One block = (batch b, i-pair). 192 threads; thread t owns j-pair (t, t+192).
// Warp-local staging: warp w cp.asyncs rows [32w, 32w+32) — exactly the rows its
// lanes read — so the main loop needs NO __syncthreads (per-warp wait_group only).
#define KC 16             // h per chunk
#define NCH (H_ / KC)     // 16 chunks
#define HUP 18            // float2 pitch per jp row (pad -> conflict-free + safe over-read)
#define HUBUF_F2 (192 * HUP)          // 3456 float2 per buffer
#define UNI_OFF_F 4096
#define SMEM_BYTES ((UNI_OFF_F + 2 * HUBUF_F2 * 2) * 4)   // 71680

__global__ __launch_bounds__(192, 3) void pair_k(
    const float* __restrict__ X, const int* __restrict__ mask,
    const float* __restrict__ Txw, const float* __restrict__ Txb,
    float* __restrict__ out)
{
    extern __shared__ float smem[];
    float4* txp  = (float4*)smem;                 // [7 ap][128 h2] quad-packed Tx
    float2* hw2  = (float2*)(smem + 3584);        // [2 i][128 h2]
    float*  uni  = smem + UNI_OFF_F;              // union: 2x hu buffers | gate buffer
    float*  gate = uni;                           // [2 i][384 j][14 a] (pre-masked, pre-biased)
    __shared__ float s_red[2][A_][4];
    __shared__ float s_ms[6];

    const int t  = threadIdx.x;
    const int w  = t >> 5, l = t & 31;
    const int b  = blockIdx.x / (L_ / 2);
    const int i0 = (blockIdx.x % (L_ / 2)) * 2;

    const uint32_t uni_u32 = (uint32_t)__cvta_generic_to_shared(uni);
    const float2* husrc = g_hu2 + (size_t)b * JP * H_;   // float2 units, [jp][h]

    // warp-local stage of one chunk: rows 32w..32w+31, 8 x 16B per row.
    // instr q: row = 32w + 4q + (l>>3), col16 = l&7 (4 rows x 128B contiguous per cp)
    const int st_row = 32 * w + (l >> 3);
    const int st_col = l & 7;

    // stage chunk 0 into buffer 0
    {
        const float2* src = husrc + st_col * 2;
        uint32_t dst = uni_u32 + (uint32_t)(st_row * HUP + st_col * 2) * 8;
        #pragma unroll
        for (int q = 0; q < 8; q++)
            cp16(dst + (uint32_t)(4 * q * HUP) * 8, src + (st_row + 4 * q) * H_);
        cp_commit();
    }

    // prologue staging: Tx quad-packed, hw h-pairs
    for (int idx = t; idx < 7 * 128; idx += 192) {
        int ap = idx >> 7, h2 = idx & 127;
        float4 v;
        v.x = Txw[(2 * ap)     * H_ + 2 * h2];
        v.y = Txw[(2 * ap + 1) * H_ + 2 * h2];
        v.z = Txw[(2 * ap)     * H_ + 2 * h2 + 1];
        v.w = Txw[(2 * ap + 1) * H_ + 2 * h2 + 1];
        txp[idx] = v;
    }
    for (int idx = t; idx < 2 * 128; idx += 192) {
        int i = idx >> 7, h2 = idx & 127;
        hw2[idx] = *(const float2*)&g_hw[(b * L_ + i0 + i) * H_ + 2 * h2];
    }

    unsigned long long acc[2][2][7];
    #pragma unroll
    for (int i = 0; i < 2; i++)
        #pragma unroll
        for (int jl = 0; jl < 2; jl++)
            #pragma unroll
            for (int ap = 0; ap < 7; ap++)
                acc[i][jl][ap] = 0ull;

    __syncthreads();   // txp/hw2 visible (chunk-0 cp is warp-local; waited below)

    for (int kc = 0; kc < NCH; kc++) {
        if (kc + 1 < NCH) {   // stage next chunk into other buffer (warp-local rows)
            uint32_t dst = uni_u32 + ((kc + 1) & 1) * (HUBUF_F2 * 8)
                         + (uint32_t)(st_row * HUP + st_col * 2) * 8;
            const float2* src = husrc + (kc + 1) * KC + st_col * 2;
            #pragma unroll
            for (int q = 0; q < 8; q++)
                cp16(dst + (uint32_t)(4 * q * HUP) * 8, src + (st_row + 4 * q) * H_);
            cp_commit();
            cp_wait<1>();    // our chunk-kc group complete (own rows only)
        } else {
            cp_wait<0>();
        }

        const float2* hu = (const float2*)uni + (kc & 1) * HUBUF_F2;
        float4 cur = *(const float4*)&hu[t * HUP];
        #pragma unroll
        for (int hl = 0; hl < KC / 2; hl++) {
            int h2 = kc * (KC / 2) + hl;   // global h/2
            // issue all smem reads for this step up front
            float4 nxt = *(const float4*)&hu[t * HUP + 2 * (hl + 1)];  // last iter reads pad
            ulonglong2 tv0 = *(const ulonglong2*)&txp[0 * 128 + h2];
            ulonglong2 tv1 = *(const ulonglong2*)&txp[1 * 128 + h2];
            ulonglong2 tv2 = *(const ulonglong2*)&txp[2 * 128 + h2];
            ulonglong2 tv3 = *(const ulonglong2*)&txp[3 * 128 + h2];
            ulonglong2 tv4 = *(const ulonglong2*)&txp[4 * 128 + h2];
            ulonglong2 tv5 = *(const ulonglong2*)&txp[5 * 128 + h2];
            ulonglong2 tv6 = *(const ulonglong2*)&txp[6 * 128 + h2];
            float2 w0 = hw2[0 * 128 + h2];
            float2 w1 = hw2[1 * 128 + h2];

            #pragma unroll
            for (int i = 0; i < 2; i++) {
                float2 wv = i ? w1 : w0;
                float r00 = fmaxf(cur.x + wv.x, 0.f);
                float r10 = fmaxf(cur.y + wv.x, 0.f);
                float r01 = fmaxf(cur.z + wv.y, 0.f);
                float r11 = fmaxf(cur.w + wv.y, 0.f);
                unsigned long long d00 = pk2(r00, r00);
                unsigned long long d10 = pk2(r10, r10);
                unsigned long long d01 = pk2(r01, r01);
                unsigned long long d11 = pk2(r11, r11);
                fma2(acc[i][0][0], d00, tv0.x); fma2(acc[i][1][0], d10, tv0.x);
                fma2(acc[i][0][0], d01, tv0.y); fma2(acc[i][1][0], d11, tv0.y);
                fma2(acc[i][0][1], d00, tv1.x); fma2(acc[i][1][1], d10, tv1.x);
                fma2(acc[i][0][1], d01, tv1.y); fma2(acc[i][1][1], d11, tv1.y);
                fma2(acc[i][0][2], d00, tv2.x); fma2(acc[i][1][2], d10, tv2.x);
                fma2(acc[i][0][2], d01, tv2.y); fma2(acc[i][1][2], d11, tv2.y);
                fma2(acc[i][0][3], d00, tv3.x); fma2(acc[i][1][3], d10, tv3.x);
                fma2(acc[i][0][3], d01, tv3.y); fma2(acc[i][1][3], d11, tv3.y);
                fma2(acc[i][0][4], d00, tv4.x); fma2(acc[i][1][4], d10, tv4.x);
                fma2(acc[i][0][4], d01, tv4.y); fma2(acc[i][1][4], d11, tv4.y);
                fma2(acc[i][0][5], d00, tv5.x); fma2(acc[i][1][5], d10, tv5.x);
                fma2(acc[i][0][5], d01, tv5.y); fma2(acc[i][1][5], d11, tv5.y);
                fma2(acc[i][0][6], d00, tv6.x); fma2(acc[i][1][6], d10, tv6.x);
                fma2(acc[i][0][6], d01, tv6.y); fma2(acc[i][1][6], d11, tv6.y);
            }
            cur = nxt;
        }
    }

    __syncthreads();   // all warps done reading hu before gate overwrites the union

    // ---- gate writeback: fold bias + mask; block msum via shuffles ----
    const float mj[2] = { (float)mask[b * L_ + t], (float)mask[b * L_ + t + JP] };
    {
        float mm = mj[0] + mj[1];
        #pragma unroll
        for (int o = 16; o; o >>= 1) mm += __shfl_xor_sync(0xffffffffu, mm, o);
        if (l == 0) s_ms[w] = mm;
    }
    #pragma unroll
    for (int i = 0; i < 2; i++)
        #pragma unroll
        for (int jl = 0; jl < 2; jl++) {
            int j = t + jl * JP;
            float m = mj[jl];
            #pragma unroll
            for (int ap = 0; ap < 7; ap++) {
                float lo, hi; upk2(acc[i][jl][ap], lo, hi);
                gate[(i * L_ + j) * A_ + 2 * ap]     = (lo + Txb[2 * ap])     * m;
                gate[(i * L_ + j) * A_ + 2 * ap + 1] = (hi + Txb[2 * ap + 1]) * m;
            }
        }
    __syncthreads();

    // phase A: reduce over j. 112 threads: (i, a, q): q<3 -> S_c, q==3 -> G
    if (t < 112) {
        int i = t / 56, r = t % 56, a = r >> 2, q = r & 3;
        float acc0 = 0.f, acc1 = 0.f;
        const float* Xb = X + (size_t)b * L_ * A_ * 3;
        #pragma unroll 4
        for (int j = 0; j < L_; j += 2) {
            float g0 = gate[(i * L_ + j)     * A_ + a];
            float g1 = gate[(i * L_ + j + 1) * A_ + a];
            if (q == 3) { acc0 += g0; acc1 += g1; }
            else {
                acc0 += g0 * Xb[((j)     * A_ + a) * 3 + q];
                acc1 += g1 * Xb[((j + 1) * A_ + a) * 3 + q];
            }
        }
        s_red[i][a][q] = acc0 + acc1;
    }
    __syncthreads();

    // phase B: 84 threads write outputs (i, a, c)
    if (t < 84) {
        int i = t / 42, r = t % 42, a = r / 3, c = r % 3;
        float denom = 1e-6f + (s_ms[0] + s_ms[1] + s_ms[2] + s_ms[3] + s_ms[4] + s_ms[5]);
        float Xi = X[((size_t)(b * L_ + i0 + i) * A_ + a) * 3 + c];
        float f = (Xi * s_red[i][a][3] - s_red[i][a][c]) / denom;
        f = fminf(fmaxf(f, -20.f), 20.f);
        out[((size_t)(b * L_ + i0 + i) * A_ + a) * 3 + c] = Xi + f;
    }
}

// ---------------- launch ----------------
extern "C" void kernel_launch(void* const* d_in, const int* in_sizes, int n_in,
                              void* d_out, int out_size) {
    const float* h    = (const float*)d_in[0];
    const float* X    = (const float*)d_in[1];
    const int*   mask = (const int*)  d_in[2];
    const float* Wxw  = (const float*)d_in[3];
    const float* Wxb  = (const float*)d_in[4];
    const float* Uxw  = (const float*)d_in[5];
    const float* Uxb  = (const float*)d_in[6];
    const float* Txw  = (const float*)d_in[7];
    const float* Txb  = (const float*)d_in[8];
    float* out = (float*)d_out;

    cudaFuncSetAttribute(pair_k, cudaFuncAttributeMaxDynamicSharedMemorySize, SMEM_BYTES);

    gemm_k<<<dim3(24, 8, 2), 128>>>(h, Wxw, Wxb, Uxw, Uxb);
    pair_k<<<dim3(B_ * (L_ / 2)), 192, SMEM_BYTES>>>(X, mask, Txw, Txb, out);
}

// round 10
// speedup vs baseline: 1.9218x; 1.5154x over previous
#include <cuda_runtime.h>
#include <cstdint>

#define B_ 2
#define L_ 384
#define H_ 256
#define A_ 14
#define BL (B_ * L_)      // 768
#define IT 4              // i's per block
#define NIG (BL / IT)     // 192 i-groups
#define NJT 3             // j-tiles of 128
#define JTL 128

// ---------------- scratch (static device globals; no allocations) ----------------
__device__ float g_hw[BL * H_];     // [bi][h]
__device__ float g_hu[BL * H_];     // [bj][h]
__device__ float g_S[BL * A_ * 4];  // [bi][a][q]: q<3 -> sum gate*m*Xj_c ; q==3 -> sum gate*m

// ---------------- helpers ----------------
__device__ __forceinline__ void cp16(uint32_t s, const void* g) {
    asm volatile("cp.async.cg.shared.global [%0], [%1], 16;" :: "r"(s), "l"(g));
}
__device__ __forceinline__ void cp_commit() { asm volatile("cp.async.commit_group;"); }
template<int N> __device__ __forceinline__ void cp_wait() {
    asm volatile("cp.async.wait_group %0;" :: "n"(N));
}
__device__ __forceinline__ uint32_t smem_u32(const void* p) {
    uint32_t a;
    asm("{ .reg .u64 t; cvta.to.shared.u64 t, %1; cvt.u32.u64 %0, t; }" : "=r"(a) : "l"(p));
    return a;
}
__device__ __forceinline__ uint32_t tf32r(float x) {
    uint32_t r;
    asm("cvt.rna.tf32.f32 %0, %1;" : "=r"(r) : "f"(x));
    return r;
}
__device__ __forceinline__ void mma_tf32(float* d, uint32_t a0, uint32_t a1,
                                         uint32_t a2, uint32_t a3,
                                         uint32_t b0, uint32_t b1) {
    asm volatile(
        "mma.sync.aligned.m16n8k8.row.col.f32.tf32.tf32.f32 "
        "{%0,%1,%2,%3}, {%4,%5,%6,%7}, {%8,%9}, {%0,%1,%2,%3};"
        : "+f"(d[0]), "+f"(d[1]), "+f"(d[2]), "+f"(d[3])
        : "r"(a0), "r"(a1), "r"(a2), "r"(a3), "r"(b0), "r"(b1));
}

// ---------------- kernel 1: hw/hu = h@W^T+b (fp32) + zero g_S ----------------
__global__ __launch_bounds__(128) void gemm_k(
    const float* __restrict__ h,
    const float* __restrict__ Wx, const float* __restrict__ Wxb,
    const float* __restrict__ Ux, const float* __restrict__ Uxb)
{
    {   // zero partial-sum accumulator (43008 floats over 49152 threads)
        int fb = blockIdx.x + 24 * (blockIdx.y + 8 * blockIdx.z);
        int gtid = fb * 128 + threadIdx.x;
        if (gtid < BL * A_ * 4) g_S[gtid] = 0.f;
    }
    const int z = blockIdx.z;
    const float* W    = z ? Ux  : Wx;
    const float* bias = z ? Uxb : Wxb;
    const int m0 = blockIdx.x * 32;
    const int n0 = blockIdx.y * 32;

    __shared__ float As[16][32];
    __shared__ float Bs[16][32];

    const int tid = threadIdx.x;
    const int tm = tid & 15, tn = tid >> 4;

    float acc[2][4] = {};

    for (int k0 = 0; k0 < H_; k0 += 16) {
        {
            int row = tid >> 2, kq = (tid & 3) * 4;
            float4 a = *(const float4*)&h[(m0 + row) * H_ + k0 + kq];
            As[kq + 0][row] = a.x; As[kq + 1][row] = a.y;
            As[kq + 2][row] = a.z; As[kq + 3][row] = a.w;
            float4 bv = *(const float4*)&W[(n0 + row) * H_ + k0 + kq];
            Bs[kq + 0][row] = bv.x; Bs[kq + 1][row] = bv.y;
            Bs[kq + 2][row] = bv.z; Bs[kq + 3][row] = bv.w;
        }
        __syncthreads();
        #pragma unroll
        for (int k = 0; k < 16; k++) {
            float2 a2 = *(const float2*)&As[k][tm * 2];
            float4 b4 = *(const float4*)&Bs[k][tn * 4];
            acc[0][0] += a2.x * b4.x; acc[0][1] += a2.x * b4.y;
            acc[0][2] += a2.x * b4.z; acc[0][3] += a2.x * b4.w;
            acc[1][0] += a2.y * b4.x; acc[1][1] += a2.y * b4.y;
            acc[1][2] += a2.y * b4.z; acc[1][3] += a2.y * b4.w;
        }
        __syncthreads();
    }

    #pragma unroll
    for (int r = 0; r < 2; r++) {
        int m = m0 + tm * 2 + r;
        #pragma unroll
        for (int c = 0; c < 4; c++) {
            int n = n0 + tn * 4 + c;
            float val = acc[r][c] + bias[n];
            if (z == 0) g_hw[m * H_ + n] = val;
            else        g_hu[m * H_ + n] = val;
        }
    }
}

// ---------------- kernel 2: tf32 mma.sync pairwise gate + partial fold ----------------
// Block = (i-group of 4) x (j-tile of 128); 256 threads = 8 warps; warp w owns
// j rows [16w, 16w+16) and loops all 4 i's (A fragments built in registers).
#define TX_F  (16 * 264)      // tf32-rounded Tx, padded pitch 264 (bank-clean)
#define HW_F  (IT * H_)       // 1024
#define HUP   36              // float pitch per j row in a 32-h chunk (bank-clean)
#define HUBUF (JTL * HUP)     // 4608 floats per buffer
#define SMEM_F (TX_F + HW_F + 2 * HUBUF)   // 14464 floats = 57856 B
#define SMEM_BYTES (SMEM_F * 4)

__global__ __launch_bounds__(256) void pair_k(
    const float* __restrict__ X, const int* __restrict__ mask,
    const float* __restrict__ Txw, const float* __restrict__ Txb)
{
    extern __shared__ float smf[];
    uint32_t* tx  = (uint32_t*)smf;            // [16][264] tf32 bits (rows 14,15 zero)
    float*    hws = smf + TX_F;                // [4][256]
    float*    hub = smf + TX_F + HW_F;         // 2 x [128][36]
    float*    xm  = hub;                       // overlay after MMA: [128][14][4]
    __shared__ float txbs[16];

    const int t = threadIdx.x, w = t >> 5, lane = t & 31;
    const int g = lane >> 2, c = lane & 3;
    const int ig = blockIdx.x, jt = blockIdx.y;
    const int ibase = ig * IT;
    const int b  = ibase / L_;
    const int j0 = jt * JTL;

    const uint32_t hub0 = smem_u32(hub);
    const float* hus = g_hu + (size_t)(b * L_ + j0) * H_;

    // stage hu chunk 0 (128 j x 32 h): 1024 cp16
    {
        #pragma unroll
        for (int q = 0; q < 4; q++) {
            int idx = t + q * 256, r = idx >> 3, c8 = idx & 7;
            cp16(hub0 + (uint32_t)(r * HUP + c8 * 4) * 4, hus + r * H_ + c8 * 4);
        }
        cp_commit();
    }
    // stage Tx (tf32-rounded), txb, hw
    for (int idx = t; idx < 16 * H_; idx += 256) {
        int a = idx >> 8, hh = idx & 255;
        float v = (a < A_) ? Txw[a * H_ + hh] : 0.f;
        tx[a * 264 + hh] = tf32r(v);
    }
    if (t < 16) txbs[t] = (t < A_) ? Txb[t] : 0.f;
    for (int idx = t; idx < IT * H_; idx += 256)
        hws[idx] = g_hw[ibase * H_ + idx];

    float acc[IT][2][4];
    #pragma unroll
    for (int i = 0; i < IT; i++)
        #pragma unroll
        for (int n = 0; n < 2; n++)
            #pragma unroll
            for (int r = 0; r < 4; r++) acc[i][n][r] = 0.f;

    const int jr0 = w * 16 + g, jr1 = jr0 + 8;

    for (int kc = 0; kc < 8; kc++) {
        if (kc < 7) {   // stage next chunk into other buffer
            uint32_t dst = hub0 + (uint32_t)(((kc + 1) & 1) * HUBUF) * 4;
            const float* src = hus + (kc + 1) * 32;
            #pragma unroll
            for (int q = 0; q < 4; q++) {
                int idx = t + q * 256, r = idx >> 3, c8 = idx & 7;
                cp16(dst + (uint32_t)(r * HUP + c8 * 4) * 4, src + r * H_ + c8 * 4);
            }
            cp_commit();
            cp_wait<1>();
        } else {
            cp_wait<0>();
        }
        __syncthreads();   // chunk kc fully staged (covers prologue at kc=0)

        const float* hb = hub + (kc & 1) * HUBUF;
        #pragma unroll
        for (int ks = 0; ks < 4; ks++) {
            const int kk = kc * 32 + ks * 8;   // global h base of this k8
            const int kl = ks * 8;             // within-chunk base
            // B fragments: b0=(k=c, n=g), b1=(k=c+4, n=g); ntile1 uses rows g+8
            uint32_t b00 = tx[g * 264 + kk + c];
            uint32_t b01 = tx[g * 264 + kk + c + 4];
            uint32_t b10 = tx[(g + 8) * 264 + kk + c];
            uint32_t b11 = tx[(g + 8) * 264 + kk + c + 4];
            // hu values for this warp's two j rows, cols c and c+4
            float h0c  = hb[jr0 * HUP + kl + c];
            float h1c  = hb[jr1 * HUP + kl + c];
            float h0c4 = hb[jr0 * HUP + kl + c + 4];
            float h1c4 = hb[jr1 * HUP + kl + c + 4];
            #pragma unroll
            for (int i = 0; i < IT; i++) {
                float wc  = hws[i * H_ + kk + c];       // broadcast
                float wc4 = hws[i * H_ + kk + c + 4];
                uint32_t a0 = tf32r(fmaxf(h0c  + wc,  0.f));
                uint32_t a1 = tf32r(fmaxf(h1c  + wc,  0.f));
                uint32_t a2 = tf32r(fmaxf(h0c4 + wc4, 0.f));
                uint32_t a3 = tf32r(fmaxf(h1c4 + wc4, 0.f));
                mma_tf32(acc[i][0], a0, a1, a2, a3, b00, b01);
                mma_tf32(acc[i][1], a0, a1, a2, a3, b10, b11);
            }
        }
        __syncthreads();   // all reads of this buffer done before restage
    }

    // ---- overlay xm = {X*m (q<3), m} onto hu region ----
    for (int idx = t; idx < JTL * A_; idx += 256) {
        int j = idx / A_, a = idx % A_;
        float m = (float)mask[b * L_ + j0 + j];
        const float* xp = X + ((size_t)(b * L_ + j0 + j) * A_ + a) * 3;
        float* d = xm + idx * 4;
        d[0] = xp[0] * m; d[1] = xp[1] * m; d[2] = xp[2] * m; d[3] = m;
    }
    __syncthreads();

    // ---- fold: gate -> per-(a,q) partials, shuffle-reduce over g, atomicAdd ----
    // D layout: d0=(jr0, a=n8+2c), d1=(jr0, n8+2c+1), d2=(jr1, n8+2c), d3=(jr1, n8+2c+1)
    const float tb[4] = { txbs[2 * c], txbs[2 * c + 1], txbs[8 + 2 * c], txbs[9 + 2 * c] };
    #pragma unroll
    for (int i = 0; i < IT; i++) {
        float f[4][4];
        #pragma unroll
        for (int s = 0; s < 4; s++)
            #pragma unroll
            for (int q = 0; q < 4; q++) f[s][q] = 0.f;

        #pragma unroll
        for (int n = 0; n < 2; n++) {
            int an = n * 8 + 2 * c;
            #pragma unroll
            for (int r = 0; r < 4; r++) {
                int jr = (r >> 1) ? jr1 : jr0;
                int a  = an + (r & 1);
                int s  = n * 2 + (r & 1);
                float v = acc[i][n][r] + tb[s];
                const float* xp = xm + (jr * A_ + a) * 4;  // a=14,15 reads stray (guarded below)
                float4 x4 = *(const float4*)xp;
                f[s][0] += v * x4.x; f[s][1] += v * x4.y;
                f[s][2] += v * x4.z; f[s][3] += v * x4.w;
            }
        }
        // reduce over g (lanes xor 4, 8, 16)
        #pragma unroll
        for (int s = 0; s < 4; s++)
            #pragma unroll
            for (int q = 0; q < 4; q++) {
                float v = f[s][q];
                v += __shfl_xor_sync(0xffffffffu, v, 4);
                v += __shfl_xor_sync(0xffffffffu, v, 8);
                v += __shfl_xor_sync(0xffffffffu, v, 16);
                f[s][q] = v;
            }
        if (lane < 4) {   // lane == c
            #pragma unroll
            for (int s = 0; s < 4; s++) {
                int a = (s >> 1) * 8 + 2 * lane + (s & 1);
                if (a < A_) {
                    #pragma unroll
                    for (int q = 0; q < 4; q++)
                        atomicAdd(&g_S[((ibase + i) * A_ + a) * 4 + q], f[s][q]);
                }
            }
        }
    }
}

// ---------------- kernel 3: finalize ----------------
__global__ void fin_k(const float* __restrict__ X, const int* __restrict__ mask,
                      float* __restrict__ out)
{
    const int bi = blockIdx.x, t = threadIdx.x;
    const int b = bi / L_;
    __shared__ float smv[64];
    float s = 0.f;
    for (int j = t; j < L_; j += 64) s += (float)mask[b * L_ + j];
    smv[t] = s;
    __syncthreads();
    if (t == 0) {
        float tot = 0.f;
        for (int k = 0; k < 64; k++) tot += smv[k];
        smv[0] = tot;
    }
    __syncthreads();
    if (t < A_ * 3) {
        int a = t / 3, c = t % 3;
        float S = g_S[(bi * A_ + a) * 4 + c];
        float G = g_S[(bi * A_ + a) * 4 + 3];
        float Xi = X[((size_t)bi * A_ + a) * 3 + c];
        float f = (Xi * G - S) / (1e-6f + smv[0]);
        f = fminf(fmaxf(f, -20.f), 20.f);
        out[((size_t)bi * A_ + a) * 3 + c] = Xi + f;
    }
}

// ---------------- launch ----------------
extern "C" void kernel_launch(void* const* d_in, const int* in_sizes, int n_in,
                              void* d_out, int out_size) {
    const float* h    = (const float*)d_in[0];
    const float* X    = (const float*)d_in[1];
    const int*   mask = (const int*)  d_in[2];
    const float* Wxw  = (const float*)d_in[3];
    const float* Wxb  = (const float*)d_in[4];
    const float* Uxw  = (const float*)d_in[5];
    const float* Uxb  = (const float*)d_in[6];
    const float* Txw  = (const float*)d_in[7];
    const float* Txb  = (const float*)d_in[8];
    float* out = (float*)d_out;

    cudaFuncSetAttribute(pair_k, cudaFuncAttributeMaxDynamicSharedMemorySize, SMEM_BYTES);

    gemm_k<<<dim3(24, 8, 2), 128>>>(h, Wxw, Wxb, Uxw, Uxb);
    pair_k<<<dim3(NIG, NJT), 256, SMEM_BYTES>>>(X, mask, Txw, Txb);
    fin_k<<<BL, 64>>>(X, mask, out);
}